// round 11
// baseline (speedup 1.0000x reference)
#include <cuda_runtime.h>
#include <cuda_fp16.h>

#define I_DIM   128
#define O_DIM   128
#define G_NUM   128
#define G1      129
#define B_DIM   8192
#define C_CHUNKS 4
#define ICHUNK  (I_DIM / C_CHUNKS)   /* 32 */
#define BT      256                  /* batch columns per block */
#define NBT     (B_DIM / BT)         /* 32 */
#define THREADS 512
#define NWARP   (THREADS / 32)       /* 16 */
#define BPW     (BT / NWARP)         /* 16 batch columns per warp */
#define ROW_U   (O_DIM / 2)          /* 64 uints per 256B fp16 row */
#define TI      16                   /* i per transpose tile */

// Static device scratch (allocation-free per harness rules)
__device__ __align__(256) __half g_P2h[(size_t)I_DIM * G1 * O_DIM];   // [i][g][o] 4.2MB
__device__ __align__(16) __half g_partialH[C_CHUNKS][B_DIM][O_DIM];   // [c][b][o] fp16 8MB

// ---------------------------------------------------------------------------
// Kernel 1 (round-10): transpose+quantize P[g][o][i] -> P2h[i][g][o].
// ---------------------------------------------------------------------------
__global__ __launch_bounds__(256, 8)
void transpose_kernel(const float* __restrict__ P) {
    __shared__ float tile[2][O_DIM][17];
    const int g0 = blockIdx.y * 2;       // 0,2,...,128
    const int i0 = blockIdx.x * TI;      // 0..112
    const int t = threadIdx.x;
    const int w = t >> 5, lane = t & 31;
    const int gg = w >> 2;               // 0..1: which g this warp serves
    const int w2 = w & 3;                // 0..3: warp within the g
    const int oq = lane >> 2;            // 0..7
    const int f4 = lane & 3;             // 0..3
    const int g = g0 + gg;

    if (g <= G_NUM) {
        const float4* src = (const float4*)(P + (size_t)g * O_DIM * I_DIM + i0);
        float4 v[4];
#pragma unroll
        for (int r = 0; r < 4; r++) {
            int o = w2 * 32 + r * 8 + oq;
            v[r] = src[(size_t)o * (I_DIM / 4) + f4];
        }
#pragma unroll
        for (int r = 0; r < 4; r++) {
            int o = w2 * 32 + r * 8 + oq;
            tile[gg][o][f4 * 4 + 0] = v[r].x;
            tile[gg][o][f4 * 4 + 1] = v[r].y;
            tile[gg][o][f4 * 4 + 2] = v[r].z;
            tile[gg][o][f4 * 4 + 3] = v[r].w;
        }
    }
    __syncthreads();

    const int op  = t & 63;          // o-pair index 0..63
    const int il  = (t >> 6) & 1;    // 0..1
    const int gg2 = t >> 7;          // 0..1
    const int gs  = g0 + gg2;
    if (gs <= G_NUM) {
        __half2* dst = (__half2*)g_P2h;
#pragma unroll
        for (int r = 0; r < 8; r++) {
            int i = il + 2 * r;          // 0..15
            dst[((size_t)(i0 + i) * G1 + gs) * (O_DIM / 2) + op] =
                __floats2half2_rn(tile[gg2][2 * op][i], tile[gg2][2 * op + 1][i]);
        }
    }
}

// ---------------------------------------------------------------------------
// Kernel 2: gather + lerp. Block = 256 b x 32 i; warp = 16 batch cols.
// NEW: all gather loads are LDG.32 (128B/warp = exactly ONE L1 wavefront
// each, avoiding the 2.07 cyc/wf within-LDG replay penalty of wider loads).
// Lane covers outputs {2l, 2l+1, 64+2l, 64+2l+1} via 4 scalar loads with
// immediate offsets off a single row pointer.
// ---------------------------------------------------------------------------
__global__ __launch_bounds__(THREADS, 1)
void main_kernel(const float* __restrict__ x,
                 const float* __restrict__ borders,
                 const float* __restrict__ invl) {
    __shared__ __align__(16) unsigned s_gd[ICHUNK][BT];   // 32 KB
    __shared__ float s_b[G1];
    __shared__ float s_il[G_NUM];

    const int t     = threadIdx.x;
    const int btile = blockIdx.x;    // 0..31
    const int chunk = blockIdx.y;    // 0..3
    const int b0    = btile * BT;
    const int i0    = chunk * ICHUNK;

    if (t < G1)    s_b[t]  = borders[t];
    if (t < G_NUM) s_il[t] = invl[t];
    __syncthreads();

    // Phase 1: bucket index g + weight d, packed (g | half(d)<<16)
    {
        const int bl    = t & (BT - 1);
        const int ibase = t >> 8;
#pragma unroll
        for (int p = 0; p < ICHUNK / 2; p++) {
            int il = ibase + 2 * p;
            float xv = x[(size_t)(i0 + il) * B_DIM + b0 + bl];
            float e  = __expf(-fabsf(xv));
            float cdf = (xv > 0.f) ? (1.f - 0.5f * e) : (0.5f * e);
            int g = (int)(cdf * (float)G_NUM);
            g = min(max(g, 0), G_NUM - 1);
            float d = (xv - s_b[g]) * s_il[g];
            unsigned db = (unsigned)__half_as_ushort(__float2half_rn(d));
            s_gd[il][bl] = (unsigned)g | (db << 16);
        }
    }
    __syncthreads();

    const int w    = t >> 5;
    const int lane = t & 31;
    const int wb   = w * BPW;

    const __half2 one2 = __floats2half2_rn(1.f, 1.f);
    const __half2 z2   = __floats2half2_rn(0.f, 0.f);
    const unsigned* __restrict__ P2u = (const unsigned*)g_P2h;

    float4 accF[BPW];
#pragma unroll
    for (int j = 0; j < BPW; j++) accF[j] = make_float4(0.f, 0.f, 0.f, 0.f);

    for (int iiB = 0; iiB < ICHUNK; iiB += 4) {
        __half2 a0[BPW], a1[BPW];
#pragma unroll
        for (int j = 0; j < BPW; j++) { a0[j] = z2; a1[j] = z2; }

#pragma unroll
        for (int u = 0; u < 4; u++) {
            const int ii = iiB + u;
            const unsigned* slice = P2u + (size_t)(i0 + ii) * (G1 * ROW_U) + lane;
#pragma unroll
            for (int j = 0; j < BPW; j++) {
                unsigned v  = s_gd[ii][wb + j];     // broadcast LDS
                unsigned gi = v & 0xFFu;
                unsigned dd = __byte_perm(v, v, 0x3232);
                __half2 d2  = *(__half2*)&dd;
                __half2 w2  = __hsub2(one2, d2);
                const unsigned* rowp = slice + gi * ROW_U;
                unsigned A0 = __ldg(rowp);              // row g,   o[0:63]   1 wf
                unsigned A1 = __ldg(rowp + 32);         // row g,   o[64:127] 1 wf
                unsigned B0 = __ldg(rowp + ROW_U);      // row g+1, o[0:63]   1 wf
                unsigned B1 = __ldg(rowp + ROW_U + 32); // row g+1, o[64:127] 1 wf
                a0[j] = __hfma2(w2, *(__half2*)&A0, a0[j]);
                a0[j] = __hfma2(d2, *(__half2*)&B0, a0[j]);
                a1[j] = __hfma2(w2, *(__half2*)&A1, a1[j]);
                a1[j] = __hfma2(d2, *(__half2*)&B1, a1[j]);
            }
        }

        // flush half2 partials into fp32 accumulators every 4 slices
#pragma unroll
        for (int j = 0; j < BPW; j++) {
            float2 p0 = __half22float2(a0[j]);
            float2 p1 = __half22float2(a1[j]);
            accF[j].x += p0.x; accF[j].y += p0.y;   // o = 2l, 2l+1
            accF[j].z += p1.x; accF[j].w += p1.y;   // o = 64+2l, 64+2l+1
        }
        if (iiB & 4) __syncthreads();
    }

    // Coalesced packed-half2 stores (two 128B STG.32 sweeps per column).
#pragma unroll
    for (int j = 0; j < BPW; j++) {
        __half2 ph0 = __floats2half2_rn(accF[j].x, accF[j].y);
        __half2 ph1 = __floats2half2_rn(accF[j].z, accF[j].w);
        unsigned* dst = (unsigned*)&g_partialH[chunk][b0 + wb + j][0];
        dst[lane]      = *(unsigned*)&ph0;    // o = 2l..2l+1
        dst[32 + lane] = *(unsigned*)&ph1;    // o = 64+2l..64+2l+1
    }
}

// ---------------------------------------------------------------------------
// Kernel 3 (round-10): sum the 4 fp16 partials, transpose -> out[o][b].
// ---------------------------------------------------------------------------
__global__ void reduce_kernel(float* __restrict__ out) {
    __shared__ float4 tile[32][33];
    const int b0 = blockIdx.x * 32;
    const int tx = threadIdx.x, ty = threadIdx.y;   // (32, 8)
    const size_t cstride = (size_t)B_DIM * (O_DIM / 4);   // in uint2

    const uint2* pbase = (const uint2*)&g_partialH[0][0][0];
#pragma unroll
    for (int r = 0; r < 4; r++) {
        int b = ty + r * 8;
        const uint2* p = pbase + (size_t)(b0 + b) * (O_DIM / 4) + tx;
        float4 s = make_float4(0.f, 0.f, 0.f, 0.f);
#pragma unroll
        for (int c = 0; c < C_CHUNKS; c++) {
            uint2 v = p[c * cstride];
            float2 f0 = __half22float2(*(const __half2*)&v.x);
            float2 f1 = __half22float2(*(const __half2*)&v.y);
            s.x += f0.x; s.y += f0.y; s.z += f1.x; s.w += f1.y;
        }
        tile[b][tx] = s;
    }
    __syncthreads();

    const float* tf = (const float*)tile;   // row stride = 132 floats
#pragma unroll
    for (int r = 0; r < 16; r++) {
        int o = ty + r * 8;
        out[(size_t)o * B_DIM + b0 + tx] = tf[tx * 132 + o];
    }
}

// ---------------------------------------------------------------------------
extern "C" void kernel_launch(void* const* d_in, const int* in_sizes, int n_in,
                              void* d_out, int out_size) {
    const float* x       = (const float*)d_in[0];   // [128, 8192]
    const float* P       = (const float*)d_in[1];   // [129, 128, 128]
    const float* borders = (const float*)d_in[2];   // [129]
    const float* invl    = (const float*)d_in[3];   // [128]
    float*       out     = (float*)d_out;           // [128, 8192]

    transpose_kernel<<<dim3(I_DIM / TI, 65), 256>>>(P);
    main_kernel<<<dim3(NBT, C_CHUNKS), THREADS>>>(x, borders, invl);
    reduce_kernel<<<B_DIM / 32, dim3(32, 8)>>>(out);
}

// round 12
// speedup vs baseline: 1.0515x; 1.0515x over previous
#include <cuda_runtime.h>
#include <cuda_fp16.h>

#define I_DIM   128
#define O_DIM   128
#define G_NUM   128
#define G1      129
#define B_DIM   8192
#define C_CHUNKS 4
#define ICHUNK  (I_DIM / C_CHUNKS)   /* 32 */
#define BT      256                  /* batch columns per block */
#define NBT     (B_DIM / BT)         /* 32 */
#define THREADS 1024
#define NWARP   (THREADS / 32)       /* 32 */
#define BPW     (BT / NWARP)         /* 8 batch columns per warp */
#define ROW_U2  (O_DIM / 4)          /* 32 uint2 per 256B fp16 row */
#define TI      16                   /* i per transpose tile */

// Static device scratch (allocation-free per harness rules)
__device__ __align__(256) __half g_P2h[(size_t)I_DIM * G1 * O_DIM];   // [i][g][o] 4.2MB
__device__ __align__(16) __half g_partialH[C_CHUNKS][B_DIM][O_DIM];   // [c][b][o] fp16 8MB

// ---------------------------------------------------------------------------
// Kernel 1 (round-10, stable): transpose+quantize P[g][o][i] -> P2h[i][g][o].
// ---------------------------------------------------------------------------
__global__ __launch_bounds__(256, 8)
void transpose_kernel(const float* __restrict__ P) {
    __shared__ float tile[2][O_DIM][17];
    const int g0 = blockIdx.y * 2;       // 0,2,...,128
    const int i0 = blockIdx.x * TI;      // 0..112
    const int t = threadIdx.x;
    const int w = t >> 5, lane = t & 31;
    const int gg = w >> 2;               // 0..1
    const int w2 = w & 3;                // 0..3
    const int oq = lane >> 2;            // 0..7
    const int f4 = lane & 3;             // 0..3
    const int g = g0 + gg;

    if (g <= G_NUM) {
        const float4* src = (const float4*)(P + (size_t)g * O_DIM * I_DIM + i0);
        float4 v[4];
#pragma unroll
        for (int r = 0; r < 4; r++) {
            int o = w2 * 32 + r * 8 + oq;
            v[r] = src[(size_t)o * (I_DIM / 4) + f4];
        }
#pragma unroll
        for (int r = 0; r < 4; r++) {
            int o = w2 * 32 + r * 8 + oq;
            tile[gg][o][f4 * 4 + 0] = v[r].x;
            tile[gg][o][f4 * 4 + 1] = v[r].y;
            tile[gg][o][f4 * 4 + 2] = v[r].z;
            tile[gg][o][f4 * 4 + 3] = v[r].w;
        }
    }
    __syncthreads();

    const int op  = t & 63;
    const int il  = (t >> 6) & 1;
    const int gg2 = t >> 7;
    const int gs  = g0 + gg2;
    if (gs <= G_NUM) {
        __half2* dst = (__half2*)g_P2h;
#pragma unroll
        for (int r = 0; r < 8; r++) {
            int i = il + 2 * r;
            dst[((size_t)(i0 + i) * G1 + gs) * (O_DIM / 2) + op] =
                __floats2half2_rn(tile[gg2][2 * op][i], tile[gg2][2 * op + 1][i]);
        }
    }
}

// ---------------------------------------------------------------------------
// Kernel 2: gather + lerp. ONE 1024-thread block per SM (32 warps) covering
// 256 b x 32 i. Warp handles 8 batch cols (acc = 32 regs/thread -> fits
// 64-reg cap). Gather = proven LDG.64 pattern. Double the warps of the
// 512-thread variant at identical L2 traffic -> hides L2 latency.
// ---------------------------------------------------------------------------
__global__ __launch_bounds__(THREADS, 1)
void main_kernel(const float* __restrict__ x,
                 const float* __restrict__ borders,
                 const float* __restrict__ invl) {
    __shared__ __align__(16) unsigned s_gd[ICHUNK][BT];   // 32 KB
    __shared__ float s_b[G1];
    __shared__ float s_il[G_NUM];

    const int t     = threadIdx.x;
    const int btile = blockIdx.x;    // 0..31
    const int chunk = blockIdx.y;    // 0..3
    const int b0    = btile * BT;
    const int i0    = chunk * ICHUNK;

    if (t < G1)    s_b[t]  = borders[t];
    if (t < G_NUM) s_il[t] = invl[t];
    __syncthreads();

    // Phase 1: bucket index g + weight d, packed (g | half(d)<<16)
    {
        const int bl    = t & (BT - 1);
        const int ibase = t >> 8;           // 0..3
#pragma unroll
        for (int p = 0; p < ICHUNK / 4; p++) {
            int il = ibase + 4 * p;
            float xv = x[(size_t)(i0 + il) * B_DIM + b0 + bl];
            float e  = __expf(-fabsf(xv));
            float cdf = (xv > 0.f) ? (1.f - 0.5f * e) : (0.5f * e);
            int g = (int)(cdf * (float)G_NUM);
            g = min(max(g, 0), G_NUM - 1);
            float d = (xv - s_b[g]) * s_il[g];
            unsigned db = (unsigned)__half_as_ushort(__float2half_rn(d));
            s_gd[il][bl] = (unsigned)g | (db << 16);
        }
    }
    __syncthreads();

    const int w    = t >> 5;
    const int lane = t & 31;
    const int wb   = w * BPW;        // 8 cols per warp

    const __half2 one2 = __floats2half2_rn(1.f, 1.f);
    const __half2 z2   = __floats2half2_rn(0.f, 0.f);
    const uint2* __restrict__ P2v = (const uint2*)g_P2h;

    float4 accF[BPW];
#pragma unroll
    for (int j = 0; j < BPW; j++) accF[j] = make_float4(0.f, 0.f, 0.f, 0.f);

    for (int iiB = 0; iiB < ICHUNK; iiB += 4) {
        __half2 a0[BPW], a1[BPW];
#pragma unroll
        for (int j = 0; j < BPW; j++) { a0[j] = z2; a1[j] = z2; }

#pragma unroll
        for (int u = 0; u < 4; u++) {
            const int ii = iiB + u;
            const uint2* slice = P2v + (size_t)(i0 + ii) * (G1 * ROW_U2);
#pragma unroll
            for (int j = 0; j < BPW; j++) {
                unsigned v  = s_gd[ii][wb + j];     // broadcast LDS
                unsigned gi = v & 0xFFu;
                unsigned dd = __byte_perm(v, v, 0x3232);
                __half2 d2  = *(__half2*)&dd;
                __half2 w2  = __hsub2(one2, d2);
                const uint2* rowp = slice + gi * ROW_U2 + lane;
                uint2 A  = __ldg(rowp);             // row g   (256B coalesced)
                uint2 Bv = __ldg(rowp + ROW_U2);    // row g+1 (adjacent)
                a0[j] = __hfma2(w2, *(__half2*)&A.x,  a0[j]);
                a0[j] = __hfma2(d2, *(__half2*)&Bv.x, a0[j]);
                a1[j] = __hfma2(w2, *(__half2*)&A.y,  a1[j]);
                a1[j] = __hfma2(d2, *(__half2*)&Bv.y, a1[j]);
            }
        }

        // flush half2 partials into fp32 accumulators every 4 slices
#pragma unroll
        for (int j = 0; j < BPW; j++) {
            float2 p0 = __half22float2(a0[j]);
            float2 p1 = __half22float2(a1[j]);
            accF[j].x += p0.x; accF[j].y += p0.y;
            accF[j].z += p1.x; accF[j].w += p1.y;
        }
        if (iiB & 4) __syncthreads();   // thinned re-convergence
    }

    // Coalesced packed-half2 (uint2) stores into [c][b][o] scratch.
#pragma unroll
    for (int j = 0; j < BPW; j++) {
        __half2 ph0 = __floats2half2_rn(accF[j].x, accF[j].y);
        __half2 ph1 = __floats2half2_rn(accF[j].z, accF[j].w);
        uint2 pk;
        pk.x = *(unsigned*)&ph0;
        pk.y = *(unsigned*)&ph1;
        ((uint2*)&g_partialH[chunk][b0 + wb + j][0])[lane] = pk;
    }
}

// ---------------------------------------------------------------------------
// Kernel 3 (round-10): sum the 4 fp16 partials, transpose -> out[o][b].
// ---------------------------------------------------------------------------
__global__ void reduce_kernel(float* __restrict__ out) {
    __shared__ float4 tile[32][33];
    const int b0 = blockIdx.x * 32;
    const int tx = threadIdx.x, ty = threadIdx.y;   // (32, 8)
    const size_t cstride = (size_t)B_DIM * (O_DIM / 4);   // in uint2

    const uint2* pbase = (const uint2*)&g_partialH[0][0][0];
#pragma unroll
    for (int r = 0; r < 4; r++) {
        int b = ty + r * 8;
        const uint2* p = pbase + (size_t)(b0 + b) * (O_DIM / 4) + tx;
        float4 s = make_float4(0.f, 0.f, 0.f, 0.f);
#pragma unroll
        for (int c = 0; c < C_CHUNKS; c++) {
            uint2 v = p[c * cstride];
            float2 f0 = __half22float2(*(const __half2*)&v.x);
            float2 f1 = __half22float2(*(const __half2*)&v.y);
            s.x += f0.x; s.y += f0.y; s.z += f1.x; s.w += f1.y;
        }
        tile[b][tx] = s;
    }
    __syncthreads();

    const float* tf = (const float*)tile;   // row stride = 132 floats
#pragma unroll
    for (int r = 0; r < 16; r++) {
        int o = ty + r * 8;
        out[(size_t)o * B_DIM + b0 + tx] = tf[tx * 132 + o];
    }
}

// ---------------------------------------------------------------------------
extern "C" void kernel_launch(void* const* d_in, const int* in_sizes, int n_in,
                              void* d_out, int out_size) {
    const float* x       = (const float*)d_in[0];   // [128, 8192]
    const float* P       = (const float*)d_in[1];   // [129, 128, 128]
    const float* borders = (const float*)d_in[2];   // [129]
    const float* invl    = (const float*)d_in[3];   // [128]
    float*       out     = (float*)d_out;           // [128, 8192]

    transpose_kernel<<<dim3(I_DIM / TI, 65), 256>>>(P);
    main_kernel<<<dim3(NBT, C_CHUNKS), THREADS>>>(x, borders, invl);
    reduce_kernel<<<B_DIM / 32, dim3(32, 8)>>>(out);
}